// round 6
// baseline (speedup 1.0000x reference)
#include <cuda_runtime.h>
#include <math.h>

#define ETA 0.1f
#define THETA 4.0f
#define NN 4096            // 64*64
#define THREADS 128        // 2 matrices per CTA, 64 threads each

typedef unsigned long long u64;

__device__ __forceinline__ u64 fma2(u64 a, u64 b, u64 c) {
    u64 d;
    asm("fma.rn.f32x2 %0, %1, %2, %3;" : "=l"(d) : "l"(a), "l"(b), "l"(c));
    return d;
}
__device__ __forceinline__ u64 dup2(float a) {
    u64 d;
    asm("mov.b64 %0, {%1, %1};" : "=l"(d) : "f"(a));
    return d;
}
__device__ __forceinline__ float2 unpk(u64 v) {
    float2 r;
    asm("mov.b64 {%0, %1}, %2;" : "=f"(r.x), "=f"(r.y) : "l"(v));
    return r;
}

// per-half barrier (64 threads = 2 warps), compile-time immediate barrier id
__device__ __forceinline__ void hbar(int m) {
    if (m == 0) asm volatile("bar.sync 1, 64;" ::: "memory");
    else        asm volatile("bar.sync 2, 64;" ::: "memory");
}

// swizzled float offset of logical (row, float4-chunk). chunk in [0,16).
__device__ __forceinline__ int sw(int r, int c) {
    return (r << 6) + ((c ^ ((r >> 2) & 6)) << 2);
}

// ---------------------------------------------------------------------------
// 64x64 GEMM, one matrix, 64 threads (t in [0,64)), 8x8 tile per thread.
// C = A*B (+ optional d0*I + d1*E1 + d2*E2 + d3*E3). STRICTLY OUT-OF-PLACE.
// av double-buffered per 4-k chunk; bv 2-slot rotating with 1-kk lookahead.
// All matrices stored with sw() swizzle. Ends with a per-half barrier.
// ---------------------------------------------------------------------------
template<bool EPI>
__device__ __forceinline__ void mm64(int m, int t, float* __restrict__ C,
                                     const float* __restrict__ A,
                                     const float* __restrict__ B,
                                     const float* __restrict__ E1,
                                     const float* __restrict__ E2,
                                     const float* __restrict__ E3,
                                     float d0, float d1, float d2, float d3)
{
    const int ty = t >> 3, tx = t & 7;
    const int r0 = ty << 3;
    const int sA = (ty & 3) << 1;       // row-swizzle value for rows r0..r0+7
    const int sc = tx ^ sA;             // stored chunk of this thread's low C chunk

    u64 acc[8][4];
#pragma unroll
    for (int i = 0; i < 8; i++) { acc[i][0] = acc[i][1] = acc[i][2] = acc[i][3] = 0ull; }

    float4 av[2][8];
    ulonglong2 bv[2][2];

    // load A chunk `cc` (4 k-values) into av[buf]
#define AVLOAD(buf, cc) do {                                                       \
        const int ao_ = (((cc) ^ sA) << 2);                                        \
        _Pragma("unroll")                                                          \
        for (int i_ = 0; i_ < 8; i_++)                                             \
            av[buf][i_] = *(const float4*)(A + ((r0 + i_) << 6) + ao_);            \
    } while (0)

    // load B row K (clamped) into bv[buf]
#define BVLOAD(buf, K) do {                                                        \
        const int kr_ = (K) < 63 ? (K) : 63;                                       \
        const int bo_ = ((tx ^ ((kr_ >> 2) & 6)) << 2);                            \
        const float* br_ = B + (kr_ << 6);                                         \
        bv[buf][0] = *(const ulonglong2*)(br_ + bo_);                              \
        bv[buf][1] = *(const ulonglong2*)(br_ + bo_ + 32);                         \
    } while (0)

    // accumulate: A column kk of av[ab] times B row in bv[bb]
#define MMCOMP(ab, bb, kk) do {                                                    \
        _Pragma("unroll")                                                          \
        for (int i_ = 0; i_ < 8; i_++) {                                           \
            const float a_ = ((const float*)&av[ab][i_])[kk];                      \
            const u64 aa_ = dup2(a_);                                              \
            acc[i_][0] = fma2(aa_, bv[bb][0].x, acc[i_][0]);                       \
            acc[i_][1] = fma2(aa_, bv[bb][0].y, acc[i_][1]);                       \
            acc[i_][2] = fma2(aa_, bv[bb][1].x, acc[i_][2]);                       \
            acc[i_][3] = fma2(aa_, bv[bb][1].y, acc[i_][3]);                       \
        }                                                                          \
    } while (0)

    // one 4-k chunk: base K = 4*cc, A in av[ab]; prefetch bv one kk ahead
#define CHUNK(ab, Kbase) do {                                                      \
        BVLOAD(1, (Kbase) + 1); MMCOMP(ab, 0, 0);                                  \
        BVLOAD(0, (Kbase) + 2); MMCOMP(ab, 1, 1);                                  \
        BVLOAD(1, (Kbase) + 3); MMCOMP(ab, 0, 2);                                  \
        BVLOAD(0, (Kbase) + 4); MMCOMP(ab, 1, 3);                                  \
    } while (0)

    AVLOAD(0, 0);
    BVLOAD(0, 0);
#pragma unroll 1
    for (int b = 0; b < 8; b++) {
        const int cc = 2 * b;
        AVLOAD(1, cc + 1);
        CHUNK(0, cc * 4);
        const int nc = (cc + 2 < 15) ? (cc + 2) : 15;
        AVLOAD(0, nc);
        CHUNK(1, (cc + 1) * 4);
    }

#undef AVLOAD
#undef BVLOAD
#undef MMCOMP
#undef CHUNK

#pragma unroll
    for (int i = 0; i < 8; i++) {
        const int row = r0 + i;
        const int offL = (row << 6) + (sc << 2);
        const int offH = offL + 32;
        const float2 p0 = unpk(acc[i][0]), p1 = unpk(acc[i][1]);
        const float2 p2 = unpk(acc[i][2]), p3 = unpk(acc[i][3]);
        float4 o0 = make_float4(p0.x, p0.y, p1.x, p1.y);
        float4 o1 = make_float4(p2.x, p2.y, p3.x, p3.y);
        if (EPI) {
            const float4 e1L = *(const float4*)(E1 + offL);
            const float4 e2L = *(const float4*)(E2 + offL);
            const float4 e3L = *(const float4*)(E3 + offL);
            const float4 e1H = *(const float4*)(E1 + offH);
            const float4 e2H = *(const float4*)(E2 + offH);
            const float4 e3H = *(const float4*)(E3 + offH);
            o0.x += fmaf(d1, e1L.x, fmaf(d2, e2L.x, d3 * e3L.x));
            o0.y += fmaf(d1, e1L.y, fmaf(d2, e2L.y, d3 * e3L.y));
            o0.z += fmaf(d1, e1L.z, fmaf(d2, e2L.z, d3 * e3L.z));
            o0.w += fmaf(d1, e1L.w, fmaf(d2, e2L.w, d3 * e3L.w));
            o1.x += fmaf(d1, e1H.x, fmaf(d2, e2H.x, d3 * e3H.x));
            o1.y += fmaf(d1, e1H.y, fmaf(d2, e2H.y, d3 * e3H.y));
            o1.z += fmaf(d1, e1H.z, fmaf(d2, e2H.z, d3 * e3H.z));
            o1.w += fmaf(d1, e1H.w, fmaf(d2, e2H.w, d3 * e3H.w));
            if ((row >> 2) == tx)     ((float*)&o0)[i & 3] += d0;
            if ((row >> 2) == tx + 8) ((float*)&o1)[i & 3] += d0;
        }
        *(float4*)(C + offL) = o0;
        *(float4*)(C + offH) = o1;
    }
    hbar(m);
}

__global__ void __launch_bounds__(THREADS, 2)
meg_update_kernel(const float* __restrict__ gR,
                  const float* __restrict__ gG,
                  float* __restrict__ gOut) {
    const int tid = threadIdx.x;
    const int m = tid >> 6;          // which matrix of this CTA
    const int t = tid & 63;

    extern __shared__ float smx[];
    float* base = smx + m * 6 * NN;
    float* bA  = base;
    float* bA2 = base + 1 * NN;
    float* bA3 = base + 2 * NN;
    float* bA4 = base + 3 * NN;
    float* bS  = base + 4 * NN;
    float* bS2 = base + 5 * NN;

    __shared__ float s_red[2][2];
    __shared__ int   s_nsq[2];

    const size_t gbase = ((size_t)blockIdx.x * 2 + m) * NN;
    const float4* R4 = (const float4*)(gR + gbase);
    const float4* G4 = (const float4*)(gG + gbase);
    float4* O4 = (float4*)(gOut + gbase);

    // ---- load G (swizzled) into bS ----
#pragma unroll
    for (int q = 0; q < 16; q++) {
        const int e4 = t + q * 64;
        const int r = e4 >> 4, c4 = e4 & 15;
        *(float4*)(bS + sw(r, c4)) = G4[e4];
    }
    hbar(m);

    // ---- A = log(R) - ETA*(G - G^T) ----
#pragma unroll
    for (int q = 0; q < 16; q++) {
        const int e4 = t + q * 64;
        const int r = e4 >> 4, c4 = e4 & 15;
        const int cb = c4 << 2;
        const float4 rv = R4[e4];
        const float4 gv = *(const float4*)(bS + sw(r, c4));
        const float gt0 = bS[sw(cb + 0, r >> 2) + (r & 3)];
        const float gt1 = bS[sw(cb + 1, r >> 2) + (r & 3)];
        const float gt2 = bS[sw(cb + 2, r >> 2) + (r & 3)];
        const float gt3 = bS[sw(cb + 3, r >> 2) + (r & 3)];
        float4 a;
        a.x = logf(rv.x) - ETA * (gv.x - gt0);
        a.y = logf(rv.y) - ETA * (gv.y - gt1);
        a.z = logf(rv.z) - ETA * (gv.z - gt2);
        a.w = logf(rv.w) - ETA * (gv.w - gt3);
        *(float4*)(bA + sw(r, c4)) = a;
    }
    hbar(m);

    // ---- inf-norm: thread t owns row t ----
    {
        float rs = 0.0f;
#pragma unroll
        for (int c = 0; c < 16; c++) {
            const float4 v = *(const float4*)(bA + sw(t, c));
            rs += fabsf(v.x) + fabsf(v.y) + fabsf(v.z) + fabsf(v.w);
        }
#pragma unroll
        for (int o = 16; o > 0; o >>= 1)
            rs = fmaxf(rs, __shfl_xor_sync(0xffffffffu, rs, o));
        if ((t & 31) == 0) s_red[m][t >> 5] = rs;
        hbar(m);
        if (t == 0) {
            const float nrm = fmaxf(s_red[m][0], s_red[m][1]);
            int s = 0;
            if (nrm > THETA && isfinite(nrm)) {
                s = (int)ceilf(log2f(nrm / THETA));
                if (s < 0) s = 0;
                if (s > 30) s = 30;
            }
            s_nsq[m] = s;
        }
        hbar(m);
    }
    const int nsq = s_nsq[m];
    const float scale = exp2f((float)-nsq);

    // ---- scale A (layout-agnostic) ----
#pragma unroll
    for (int q = 0; q < 16; q++) {
        float4* p = (float4*)bA + (t + q * 64);
        float4 v = *p;
        v.x *= scale; v.y *= scale; v.z *= scale; v.w *= scale;
        *p = v;
    }
    hbar(m);

    // ---- powers: A2 = A*A, A3 = A2*A, A4 = A2*A2 ----
    mm64<false>(m, t, bA2, bA,  bA,  0, 0, 0, 0.f, 0.f, 0.f, 0.f);
    mm64<false>(m, t, bA3, bA2, bA,  0, 0, 0, 0.f, 0.f, 0.f, 0.f);
    mm64<false>(m, t, bA4, bA2, bA2, 0, 0, 0, 0.f, 0.f, 0.f, 0.f);

    // Taylor 1/k! coefficients
    const float c0  = 1.0f, c1 = 1.0f, c2 = 0.5f;
    const float c3  = (float)(1.0 / 6.0),            c4c = (float)(1.0 / 24.0);
    const float c5  = (float)(1.0 / 120.0),          c6 = (float)(1.0 / 720.0);
    const float c7  = (float)(1.0 / 5040.0),         c8 = (float)(1.0 / 40320.0);
    const float c9  = (float)(1.0 / 362880.0),       c10 = (float)(1.0 / 3628800.0);
    const float c11 = (float)(1.0 / 39916800.0),     c12 = (float)(1.0 / 479001600.0);
    const float c13 = (float)(1.0 / 6227020800.0),   c14 = (float)(1.0 / 87178291200.0);
    const float c15 = (float)(1.0 / 1307674368000.0);
    const float c16 = (float)(1.0 / 20922789888000.0);

    // ---- S = c12 I + c13 A + c14 A2 + c15 A3 + c16 A4 ----
#pragma unroll
    for (int q = 0; q < 16; q++) {
        const int e4 = t + q * 64;
        const int r = e4 >> 4, c4 = e4 & 15;
        const int off = sw(r, c4);
        const float4 a  = *(const float4*)(bA  + off);
        const float4 a2 = *(const float4*)(bA2 + off);
        const float4 a3 = *(const float4*)(bA3 + off);
        const float4 a4 = *(const float4*)(bA4 + off);
        float4 s;
        s.x = fmaf(c13, a.x, fmaf(c14, a2.x, fmaf(c15, a3.x, c16 * a4.x)));
        s.y = fmaf(c13, a.y, fmaf(c14, a2.y, fmaf(c15, a3.y, c16 * a4.y)));
        s.z = fmaf(c13, a.z, fmaf(c14, a2.z, fmaf(c15, a3.z, c16 * a4.z)));
        s.w = fmaf(c13, a.w, fmaf(c14, a2.w, fmaf(c15, a3.w, c16 * a4.w)));
        if ((r >> 2) == c4) ((float*)&s)[r & 3] += c12;
        *(float4*)(bS + off) = s;
    }
    hbar(m);

    // ---- 3 Horner steps, ping-pong out-of-place ----
    mm64<true>(m, t, bS2, bA4, bS,  bA, bA2, bA3, c8,  c9, c10, c11);
    mm64<true>(m, t, bS,  bA4, bS2, bA, bA2, bA3, c4c, c5, c6,  c7);
    mm64<true>(m, t, bS2, bA4, bS,  bA, bA2, bA3, c0,  c1, c2,  c3);

    // ---- squarings: ping-pong bS2 <-> bS ----
    float* src = bS2;
    float* dst = bS;
#pragma unroll 1
    for (int q = 0; q < nsq; q++) {
        mm64<false>(m, t, dst, src, src, 0, 0, 0, 0.f, 0.f, 0.f, 0.f);
        float* tmp = src; src = dst; dst = tmp;
    }

    // ---- store (de-swizzle) ----
#pragma unroll
    for (int q = 0; q < 16; q++) {
        const int e4 = t + q * 64;
        const int r = e4 >> 4, c4 = e4 & 15;
        O4[e4] = *(const float4*)(src + sw(r, c4));
    }
}

extern "C" void kernel_launch(void* const* d_in, const int* in_sizes, int n_in,
                              void* d_out, int out_size) {
    const float* R = (const float*)d_in[0];
    const float* G = (const float*)d_in[1];
    float* out = (float*)d_out;

    const int batch = in_sizes[0] / NN;              // 8192
    const int grid = batch / 2;                      // 2 matrices per CTA
    const size_t smem = 2 * 6 * NN * sizeof(float);  // 192 KB

    static bool attr_set = false;
    if (!attr_set) {
        cudaFuncSetAttribute(meg_update_kernel,
                             cudaFuncAttributeMaxDynamicSharedMemorySize,
                             (int)smem);
        attr_set = true;
    }

    meg_update_kernel<<<grid, THREADS, smem>>>(R, G, out);
}

// round 7
// speedup vs baseline: 1.0302x; 1.0302x over previous
#include <cuda_runtime.h>
#include <math.h>

#define ETA 0.1f
#define THETA 4.0f
#define NN 4096            // 64*64
#define THREADS 128        // 2 matrices per CTA, 64 threads each

typedef unsigned long long u64;

__device__ __forceinline__ u64 fma2(u64 a, u64 b, u64 c) {
    u64 d;
    asm("fma.rn.f32x2 %0, %1, %2, %3;" : "=l"(d) : "l"(a), "l"(b), "l"(c));
    return d;
}
__device__ __forceinline__ u64 dup2(float a) {
    u64 d;
    asm("mov.b64 %0, {%1, %1};" : "=l"(d) : "f"(a));
    return d;
}
__device__ __forceinline__ float2 unpk(u64 v) {
    float2 r;
    asm("mov.b64 {%0, %1}, %2;" : "=f"(r.x), "=f"(r.y) : "l"(v));
    return r;
}

// per-half barrier (64 threads = 2 warps), compile-time immediate barrier id
__device__ __forceinline__ void hbar(int m) {
    if (m == 0) asm volatile("bar.sync 1, 64;" ::: "memory");
    else        asm volatile("bar.sync 2, 64;" ::: "memory");
}

// swizzled float offset of logical (row, float4-chunk). chunk in [0,16).
__device__ __forceinline__ int sw(int r, int c) {
    return (r << 6) + ((c ^ ((r >> 2) & 6)) << 2);
}

__global__ void __launch_bounds__(THREADS, 1)
meg_update_kernel(const float* __restrict__ gR,
                  const float* __restrict__ gG,
                  float* __restrict__ gOut) {
    const int tid = threadIdx.x;
    const int m = tid >> 6;          // which matrix of this CTA
    const int t = tid & 63;

    extern __shared__ float smx[];
    float* base = smx + m * 6 * NN;
    float* bA  = base;
    float* bA2 = base + 1 * NN;
    float* bA3 = base + 2 * NN;
    float* bA4 = base + 3 * NN;
    float* bS  = base + 4 * NN;
    float* bS2 = base + 5 * NN;

    __shared__ float s_red[2][2];
    __shared__ int   s_nsq[2];

    const size_t gbase = ((size_t)blockIdx.x * 2 + m) * NN;
    const float4* R4 = (const float4*)(gR + gbase);
    const float4* G4 = (const float4*)(gG + gbase);
    float4* O4 = (float4*)(gOut + gbase);

    // ---- load G (swizzled) into bS ----
#pragma unroll
    for (int q = 0; q < 16; q++) {
        const int e4 = t + q * 64;
        const int r = e4 >> 4, c4 = e4 & 15;
        *(float4*)(bS + sw(r, c4)) = G4[e4];
    }
    hbar(m);

    // ---- A = log(R) - ETA*(G - G^T) ----
#pragma unroll
    for (int q = 0; q < 16; q++) {
        const int e4 = t + q * 64;
        const int r = e4 >> 4, c4 = e4 & 15;
        const int cb = c4 << 2;
        const float4 rv = R4[e4];
        const float4 gv = *(const float4*)(bS + sw(r, c4));
        const float gt0 = bS[sw(cb + 0, r >> 2) + (r & 3)];
        const float gt1 = bS[sw(cb + 1, r >> 2) + (r & 3)];
        const float gt2 = bS[sw(cb + 2, r >> 2) + (r & 3)];
        const float gt3 = bS[sw(cb + 3, r >> 2) + (r & 3)];
        float4 a;
        a.x = logf(rv.x) - ETA * (gv.x - gt0);
        a.y = logf(rv.y) - ETA * (gv.y - gt1);
        a.z = logf(rv.z) - ETA * (gv.z - gt2);
        a.w = logf(rv.w) - ETA * (gv.w - gt3);
        *(float4*)(bA + sw(r, c4)) = a;
    }
    hbar(m);

    // ---- inf-norm: thread t owns row t ----
    {
        float rs = 0.0f;
#pragma unroll
        for (int c = 0; c < 16; c++) {
            const float4 v = *(const float4*)(bA + sw(t, c));
            rs += fabsf(v.x) + fabsf(v.y) + fabsf(v.z) + fabsf(v.w);
        }
#pragma unroll
        for (int o = 16; o > 0; o >>= 1)
            rs = fmaxf(rs, __shfl_xor_sync(0xffffffffu, rs, o));
        if ((t & 31) == 0) s_red[m][t >> 5] = rs;
        hbar(m);
        if (t == 0) {
            const float nrm = fmaxf(s_red[m][0], s_red[m][1]);
            int s = 0;
            if (nrm > THETA && isfinite(nrm)) {
                s = (int)ceilf(log2f(nrm / THETA));
                if (s < 0) s = 0;
                if (s > 30) s = 30;
            }
            s_nsq[m] = s;
        }
        hbar(m);
    }
    const int nsq = s_nsq[m];
    const float scale = exp2f((float)-nsq);

    // ---- scale A ----
#pragma unroll
    for (int q = 0; q < 16; q++) {
        float4* p = (float4*)bA + (t + q * 64);
        float4 v = *p;
        v.x *= scale; v.y *= scale; v.z *= scale; v.w *= scale;
        *p = v;
    }
    hbar(m);

    // Taylor 1/k! coefficients
    const float c0  = 1.0f, c1 = 1.0f, c2 = 0.5f;
    const float c3  = (float)(1.0 / 6.0),            c4c = (float)(1.0 / 24.0);
    const float c5  = (float)(1.0 / 120.0),          c6 = (float)(1.0 / 720.0);
    const float c7  = (float)(1.0 / 5040.0),         c8 = (float)(1.0 / 40320.0);
    const float c9  = (float)(1.0 / 362880.0),       c10 = (float)(1.0 / 3628800.0);
    const float c11 = (float)(1.0 / 39916800.0),     c12 = (float)(1.0 / 479001600.0);
    const float c13 = (float)(1.0 / 6227020800.0),   c14 = (float)(1.0 / 87178291200.0);
    const float c15 = (float)(1.0 / 1307674368000.0);
    const float c16 = (float)(1.0 / 20922789888000.0);

    // ---- S = c12 I + c13 A + c14 A2 + c15 A3 + c16 A4 ----
    // (A2..A4 not computed yet; computed in the step loop below BEFORE the
    //  Horner steps, so this seed only uses A. Instead we seed S after powers.)

    // ---- unified GEMM step loop: ONE inlined GEMM instance ----
    const int ty = t >> 3, tx = t & 7;
    const int r0 = ty << 3;
    const int sA = (ty & 3) << 1;
    const int sc = tx ^ sA;

    const int nsteps = 6 + nsq;
#pragma unroll 1
    for (int step = 0; step < nsteps; step++) {
        // --- pointer / coefficient selection (uniform across warp) ---
        float* C; const float* A; const float* B;
        float d0 = 0.f, d1 = 0.f, d2 = 0.f, d3 = 0.f;
        bool epi = false;
        if (step == 0)      { C = bA2; A = bA;  B = bA;  }
        else if (step == 1) { C = bA3; A = bA2; B = bA;  }
        else if (step == 2) { C = bA4; A = bA2; B = bA2; }
        else if (step < 6) {
            const int h = step - 3;
            A = bA4;
            if (h == 1) { B = bS2; C = bS; }
            else        { B = bS;  C = bS2; }
            epi = true;
            d0 = (h == 0) ? c8  : (h == 1) ? c4c : c0;
            d1 = (h == 0) ? c9  : (h == 1) ? c5  : c1;
            d2 = (h == 0) ? c10 : (h == 1) ? c6  : c2;
            d3 = (h == 0) ? c11 : (h == 1) ? c7  : c3;
        } else {
            if ((step & 1) == 0) { A = bS2; B = bS2; C = bS; }
            else                 { A = bS;  B = bS;  C = bS2; }
        }

        // --- seed S right after the powers are ready (before first Horner) ---
        if (step == 3) {
#pragma unroll
            for (int q = 0; q < 16; q++) {
                const int e4 = t + q * 64;
                const int r = e4 >> 4, c4 = e4 & 15;
                const int off = sw(r, c4);
                const float4 a  = *(const float4*)(bA  + off);
                const float4 a2 = *(const float4*)(bA2 + off);
                const float4 a3 = *(const float4*)(bA3 + off);
                const float4 a4 = *(const float4*)(bA4 + off);
                float4 s;
                s.x = fmaf(c13, a.x, fmaf(c14, a2.x, fmaf(c15, a3.x, c16 * a4.x)));
                s.y = fmaf(c13, a.y, fmaf(c14, a2.y, fmaf(c15, a3.y, c16 * a4.y)));
                s.z = fmaf(c13, a.z, fmaf(c14, a2.z, fmaf(c15, a3.z, c16 * a4.z)));
                s.w = fmaf(c13, a.w, fmaf(c14, a2.w, fmaf(c15, a3.w, c16 * a4.w)));
                if ((r >> 2) == c4) ((float*)&s)[r & 3] += c12;
                *(float4*)(bS + off) = s;
            }
            hbar(m);
        }

        // --- the single GEMM instance ---
        u64 acc[8][4];
#pragma unroll
        for (int i = 0; i < 8; i++) { acc[i][0] = acc[i][1] = acc[i][2] = acc[i][3] = 0ull; }

        float4 av[2][8];
        ulonglong2 bv[2][2];

#define AVLOAD(buf, cc) do {                                                       \
        const int ao_ = (((cc) ^ sA) << 2);                                        \
        _Pragma("unroll")                                                          \
        for (int i_ = 0; i_ < 8; i_++)                                             \
            av[buf][i_] = *(const float4*)(A + ((r0 + i_) << 6) + ao_);            \
    } while (0)

#define BVLOAD(buf, K) do {                                                        \
        const int kr_ = (K) < 63 ? (K) : 63;                                       \
        const int bo_ = ((tx ^ ((kr_ >> 2) & 6)) << 2);                            \
        const float* br_ = B + (kr_ << 6);                                         \
        bv[buf][0] = *(const ulonglong2*)(br_ + bo_);                              \
        bv[buf][1] = *(const ulonglong2*)(br_ + bo_ + 32);                         \
    } while (0)

#define MMCOMP(ab, bb, kk) do {                                                    \
        _Pragma("unroll")                                                          \
        for (int i_ = 0; i_ < 8; i_++) {                                           \
            const float a_ = ((const float*)&av[ab][i_])[kk];                      \
            const u64 aa_ = dup2(a_);                                              \
            acc[i_][0] = fma2(aa_, bv[bb][0].x, acc[i_][0]);                       \
            acc[i_][1] = fma2(aa_, bv[bb][0].y, acc[i_][1]);                       \
            acc[i_][2] = fma2(aa_, bv[bb][1].x, acc[i_][2]);                       \
            acc[i_][3] = fma2(aa_, bv[bb][1].y, acc[i_][3]);                       \
        }                                                                          \
    } while (0)

#define CHUNK(ab, Kbase) do {                                                      \
        BVLOAD(1, (Kbase) + 1); MMCOMP(ab, 0, 0);                                  \
        BVLOAD(0, (Kbase) + 2); MMCOMP(ab, 1, 1);                                  \
        BVLOAD(1, (Kbase) + 3); MMCOMP(ab, 0, 2);                                  \
        BVLOAD(0, (Kbase) + 4); MMCOMP(ab, 1, 3);                                  \
    } while (0)

        AVLOAD(0, 0);
        BVLOAD(0, 0);
#pragma unroll 1
        for (int b = 0; b < 8; b++) {
            const int cc = 2 * b;
            AVLOAD(1, cc + 1);
            CHUNK(0, cc * 4);
            const int nc = (cc + 2 < 15) ? (cc + 2) : 15;
            AVLOAD(0, nc);
            CHUNK(1, (cc + 1) * 4);
        }

#undef AVLOAD
#undef BVLOAD
#undef MMCOMP
#undef CHUNK

        // --- epilogue + store ---
#pragma unroll
        for (int i = 0; i < 8; i++) {
            const int row = r0 + i;
            const int offL = (row << 6) + (sc << 2);
            const int offH = offL + 32;
            const float2 p0 = unpk(acc[i][0]), p1 = unpk(acc[i][1]);
            const float2 p2 = unpk(acc[i][2]), p3 = unpk(acc[i][3]);
            float4 o0 = make_float4(p0.x, p0.y, p1.x, p1.y);
            float4 o1 = make_float4(p2.x, p2.y, p3.x, p3.y);
            if (epi) {
                const float4 e1L = *(const float4*)(bA  + offL);
                const float4 e2L = *(const float4*)(bA2 + offL);
                const float4 e3L = *(const float4*)(bA3 + offL);
                const float4 e1H = *(const float4*)(bA  + offH);
                const float4 e2H = *(const float4*)(bA2 + offH);
                const float4 e3H = *(const float4*)(bA3 + offH);
                o0.x += fmaf(d1, e1L.x, fmaf(d2, e2L.x, d3 * e3L.x));
                o0.y += fmaf(d1, e1L.y, fmaf(d2, e2L.y, d3 * e3L.y));
                o0.z += fmaf(d1, e1L.z, fmaf(d2, e2L.z, d3 * e3L.z));
                o0.w += fmaf(d1, e1L.w, fmaf(d2, e2L.w, d3 * e3L.w));
                o1.x += fmaf(d1, e1H.x, fmaf(d2, e2H.x, d3 * e3H.x));
                o1.y += fmaf(d1, e1H.y, fmaf(d2, e2H.y, d3 * e3H.y));
                o1.z += fmaf(d1, e1H.z, fmaf(d2, e2H.z, d3 * e3H.z));
                o1.w += fmaf(d1, e1H.w, fmaf(d2, e2H.w, d3 * e3H.w));
                if ((row >> 2) == tx)     ((float*)&o0)[i & 3] += d0;
                if ((row >> 2) == tx + 8) ((float*)&o1)[i & 3] += d0;
            }
            *(float4*)(C + offL) = o0;
            *(float4*)(C + offH) = o1;
        }
        hbar(m);
    }

    // ---- store (de-swizzle): result in bS2 if nsq even, else bS ----
    const float* src = (nsq & 1) ? bS : bS2;
#pragma unroll
    for (int q = 0; q < 16; q++) {
        const int e4 = t + q * 64;
        const int r = e4 >> 4, c4 = e4 & 15;
        O4[e4] = *(const float4*)(src + sw(r, c4));
    }
}

extern "C" void kernel_launch(void* const* d_in, const int* in_sizes, int n_in,
                              void* d_out, int out_size) {
    const float* R = (const float*)d_in[0];
    const float* G = (const float*)d_in[1];
    float* out = (float*)d_out;

    const int batch = in_sizes[0] / NN;              // 8192
    const int grid = batch / 2;                      // 2 matrices per CTA
    const size_t smem = 2 * 6 * NN * sizeof(float);  // 192 KB

    static bool attr_set = false;
    if (!attr_set) {
        cudaFuncSetAttribute(meg_update_kernel,
                             cudaFuncAttributeMaxDynamicSharedMemorySize,
                             (int)smem);
        attr_set = true;
    }

    meg_update_kernel<<<grid, THREADS, smem>>>(R, G, out);
}